// round 13
// baseline (speedup 1.0000x reference)
#include <cuda_runtime.h>
#include <cuda_bf16.h>
#include <cstdint>

#define NB 8
#define SS 2048
#define DD 800

// ---------------------------------------------------------------------------
// Scratch (__device__ globals; no allocations allowed)
// ---------------------------------------------------------------------------
__device__ __nv_bfloat16 g_h_hi [(size_t)NB * SS * DD];
__device__ __nv_bfloat16 g_h_lo [(size_t)NB * SS * DD];
__device__ __nv_bfloat16 g_ht_hi[(size_t)NB * DD * SS];
__device__ __nv_bfloat16 g_ht_lo[(size_t)NB * DD * SS];
__device__ __nv_bfloat16 g_Wt_hi[(size_t)DD * DD];
__device__ __nv_bfloat16 g_Wt_lo[(size_t)DD * DD];
__device__ __nv_bfloat16 g_hW_hi[(size_t)NB * SS * DD];
__device__ __nv_bfloat16 g_hW_lo[(size_t)NB * SS * DD];
__device__ float         g_scores[(size_t)NB * SS * SS];
__device__ __nv_bfloat16 g_P_hi [(size_t)NB * SS * SS];
__device__ __nv_bfloat16 g_P_lo [(size_t)NB * SS * SS];

// ---------------------------------------------------------------------------
// PTX helpers (baseline sm_80+ ops only: cp.async, ldmatrix, mma.sync)
// ---------------------------------------------------------------------------
__device__ __forceinline__ uint32_t smem_u32(const void* p) {
    uint32_t a;
    asm("{ .reg .u64 t; cvta.to.shared.u64 t, %1; cvt.u32.u64 %0, t; }"
        : "=r"(a) : "l"(p));
    return a;
}

__device__ __forceinline__ void cpa16(uint32_t dst, const void* src, uint32_t sz) {
    asm volatile("cp.async.cg.shared.global [%0], [%1], 16, %2;"
                 :: "r"(dst), "l"(src), "r"(sz));
}

__device__ __forceinline__ void ldsm4(uint32_t* r, uint32_t addr) {
    asm volatile("ldmatrix.sync.aligned.m8n8.x4.shared.b16 {%0,%1,%2,%3}, [%4];"
                 : "=r"(r[0]), "=r"(r[1]), "=r"(r[2]), "=r"(r[3]) : "r"(addr));
}

__device__ __forceinline__ void mma16816(float* c, const uint32_t* a, const uint32_t* b) {
    asm volatile(
        "mma.sync.aligned.m16n8k16.row.col.f32.bf16.bf16.f32 "
        "{%0,%1,%2,%3}, {%4,%5,%6,%7}, {%8,%9}, {%0,%1,%2,%3};"
        : "+f"(c[0]), "+f"(c[1]), "+f"(c[2]), "+f"(c[3])
        : "r"(a[0]), "r"(a[1]), "r"(a[2]), "r"(a[3]), "r"(b[0]), "r"(b[1]));
}

// ---------------------------------------------------------------------------
// Split-bf16 NT GEMM: C[M,N] = A[M,K] @ B[N,K]^T (both K-contiguous)
// A ~ Ahi+Alo, B ~ Bhi+Blo; C = AhiBhi + AhiBlo + AloBhi (fp32 accum)
// CTA tile 128x128, BK=32, 8 warps (2x4 grid, 64x32 each), 2-stage cp.async,
// TWO CTAs per SM; explicit register-stage pipelining of fragments.
// K % 8 == 0 and M % 128 == 0 required (true for all call sites).
// ---------------------------------------------------------------------------
static constexpr int LDSB   = 80;            // 32 bf16 padded to 80 bytes
static constexpr int MATB   = 128 * LDSB;    // 10240 B per matrix tile
static constexpr int STAGEB = 4 * MATB;      // Ahi,Alo,Bhi,Blo = 40960 B
static constexpr int GEMM_SMEM = 2 * STAGEB; // 81920 B -> 2 CTAs/SM fit

template <bool SPLIT_OUT>
__global__ __launch_bounds__(256, 2)
void gemm_mma(const __nv_bfloat16* __restrict__ Ahi, const __nv_bfloat16* __restrict__ Alo,
              const __nv_bfloat16* __restrict__ Bhi, const __nv_bfloat16* __restrict__ Blo,
              float* __restrict__ C,
              __nv_bfloat16* __restrict__ Chi, __nv_bfloat16* __restrict__ Clo,
              int N, int K, int lda, int ldb, int ldc,
              long long sA, long long sB, long long sC)
{
    extern __shared__ char smem[];
    const uint32_t sb = smem_u32(smem);
    const int tid = threadIdx.x;
    const int wid = tid >> 5, lane = tid & 31;
    const int wm = wid >> 2, wn = wid & 3;          // 2 x 4 warp grid, 64x32 tiles
    const int mBase = blockIdx.y * 128;
    const int nBase = blockIdx.x * 128;

    Ahi += (long long)blockIdx.z * sA;
    Alo += (long long)blockIdx.z * sA;
    Bhi += (long long)blockIdx.z * sB;
    Blo += (long long)blockIdx.z * sB;
    if (SPLIT_OUT) { Chi += (long long)blockIdx.z * sC; Clo += (long long)blockIdx.z * sC; }
    else           { C   += (long long)blockIdx.z * sC; }

    // A ldsm4: 16 m-rows x k16 per instr
    const uint32_t aOff = (uint32_t)((wm * 64 + (lane & 15)) * LDSB + ((lane >> 4) * 16));
    // B ldsm4: 16 n-rows x k16 per instr (two n8 frags per instr)
    const uint32_t bOff = (uint32_t)((wn * 32 + (((lane >> 4) & 1) << 3) + (lane & 7)) * LDSB
                                     + (((lane >> 3) & 1) * 16));

    float acc[4][4][4];
#pragma unroll
    for (int mt = 0; mt < 4; ++mt)
#pragma unroll
        for (int nt = 0; nt < 4; ++nt)
#pragma unroll
            for (int r = 0; r < 4; ++r) acc[mt][nt][r] = 0.f;

    const int NC = (K + 31) >> 5;

    auto load_chunk = [&](int st, int c) {
        const uint32_t base = sb + (uint32_t)st * STAGEB;
        const int k0 = c * 32;
#pragma unroll
        for (int i = 0; i < 8; ++i) {
            const int u = tid + i * 256;             // 0..2047
            const int mat = u >> 9;                  // 0..3
            const int rem = u & 511;
            const int row = rem >> 2;                // 0..127
            const int kc = rem & 3;                  // 0..3 (16B chunks)
            const uint32_t dst = base + (uint32_t)(mat * MATB + row * LDSB + kc * 16);
            const int k = k0 + kc * 8;
            const bool kok = k < K;
            if (mat < 2) {
                const __nv_bfloat16* src =
                    (mat ? Alo : Ahi) + (size_t)(mBase + row) * lda + (kok ? k : 0);
                cpa16(dst, src, kok ? 16u : 0u);     // src-size 0 -> zero fill
            } else {
                const int nr = nBase + row;
                const bool ok = kok && (nr < N);
                const __nv_bfloat16* src =
                    (mat == 3 ? Blo : Bhi) + (size_t)((nr < N) ? nr : 0) * ldb + (kok ? k : 0);
                cpa16(dst, src, ok ? 16u : 0u);
            }
        }
        asm volatile("cp.async.commit_group;" ::: "memory");
    };

    load_chunk(0, 0);

    for (int c = 0; c < NC; ++c) {
        asm volatile("cp.async.wait_group 0;" ::: "memory");
        __syncthreads();   // all warps done reading the other stage; chunk c landed

        const uint32_t base = sb + (uint32_t)(c & 1) * STAGEB;

#pragma unroll
        for (int ks = 0; ks < 2; ++ks) {
            const uint32_t ksb = (uint32_t)(ks * 32); // byte offset within row

            // --- fragment preload for this kstep (issued before anything else)
            uint32_t bh[4][2], bl[4][2];
#pragma unroll
            for (int np = 0; np < 2; ++np) {          // each ldsm4 fills two n8 frags
                ldsm4(&bh[np * 2][0], base + 2 * MATB + bOff + (uint32_t)(np * 16 * LDSB) + ksb);
                ldsm4(&bl[np * 2][0], base + 3 * MATB + bOff + (uint32_t)(np * 16 * LDSB) + ksb);
            }
            uint32_t ah[2][4];                        // A-hi double buffer
            uint32_t al[4];                           // A-lo single buffer
            ldsm4(ah[0], base + aOff + ksb);
            ldsm4(al, base + MATB + aOff + ksb);

            // issue next chunk's cp.async AFTER the first fragment LDSMs
            if (ks == 0 && c + 1 < NC) load_chunk((c + 1) & 1, c + 1);

#pragma unroll
            for (int mt = 0; mt < 4; ++mt) {
                const int cur = mt & 1, nxt = cur ^ 1;
                // prefetch next mt's A-hi before this mt's MMA burst
                if (mt < 3)
                    ldsm4(ah[nxt], base + aOff + (uint32_t)((mt + 1) * 16 * LDSB) + ksb);
#pragma unroll
                for (int nt = 0; nt < 4; ++nt)
                    mma16816(acc[mt][nt], ah[cur], bh[nt]);
#pragma unroll
                for (int nt = 0; nt < 4; ++nt)
                    mma16816(acc[mt][nt], ah[cur], bl[nt]);
#pragma unroll
                for (int nt = 0; nt < 4; ++nt)
                    mma16816(acc[mt][nt], al, bh[nt]);
                // al consumed -> reload for next mt (hidden by next mt's 32 MMAs)
                if (mt < 3)
                    ldsm4(al, base + MATB + aOff + (uint32_t)((mt + 1) * 16 * LDSB) + ksb);
            }
        }
    }

    // epilogue: direct global stores from register fragments
    const int rowA = mBase + wm * 64 + (lane >> 2);
    const int colA = nBase + wn * 32 + (lane & 3) * 2;
#pragma unroll
    for (int mt = 0; mt < 4; ++mt) {
#pragma unroll
        for (int nt = 0; nt < 4; ++nt) {
            const int col = colA + nt * 8;
            if (col < N) {
#pragma unroll
                for (int half = 0; half < 2; ++half) {
                    const int row = rowA + mt * 16 + half * 8;
                    const float v0 = acc[mt][nt][half * 2 + 0];
                    const float v1 = acc[mt][nt][half * 2 + 1];
                    const size_t off = (size_t)row * ldc + col;
                    if (SPLIT_OUT) {
                        const __nv_bfloat16 h0 = __float2bfloat16(v0);
                        const __nv_bfloat16 h1 = __float2bfloat16(v1);
                        const __nv_bfloat16 l0 = __float2bfloat16(v0 - __bfloat162float(h0));
                        const __nv_bfloat16 l1 = __float2bfloat16(v1 - __bfloat162float(h1));
                        *(__nv_bfloat162*)(Chi + off) = __halves2bfloat162(h0, h1);
                        *(__nv_bfloat162*)(Clo + off) = __halves2bfloat162(l0, l1);
                    } else {
                        *(float2*)(C + off) = make_float2(v0, v1);
                    }
                }
            }
        }
    }
}

// ---------------------------------------------------------------------------
// fp32 -> (bf16 hi, bf16 lo) elementwise split
// ---------------------------------------------------------------------------
__global__ __launch_bounds__(256)
void split2(const float* __restrict__ x, __nv_bfloat16* __restrict__ hi,
            __nv_bfloat16* __restrict__ lo, size_t n)
{
    size_t i = (size_t)blockIdx.x * 256 + threadIdx.x;
    const size_t stride = (size_t)gridDim.x * 256;
    for (; i < n; i += stride) {
        const float v = x[i];
        const __nv_bfloat16 h = __float2bfloat16(v);
        hi[i] = h;
        lo[i] = __float2bfloat16(v - __bfloat162float(h));
    }
}

// ---------------------------------------------------------------------------
// Transpose fp32 [R,Cc] -> bf16 hi/lo [Cc,R] (batched over z)
// ---------------------------------------------------------------------------
__global__ __launch_bounds__(256)
void transpose_split(const float* __restrict__ in, __nv_bfloat16* __restrict__ ohi,
                     __nv_bfloat16* __restrict__ olo, int R, int Cc,
                     long long sIn, long long sOut)
{
    __shared__ float t[32][33];
    in  += (long long)blockIdx.z * sIn;
    ohi += (long long)blockIdx.z * sOut;
    olo += (long long)blockIdx.z * sOut;
    const int c0 = blockIdx.x * 32, r0 = blockIdx.y * 32;
    const int tx = threadIdx.x, ty = threadIdx.y;   // (32, 8)
#pragma unroll
    for (int i = 0; i < 32; i += 8)
        t[ty + i][tx] = in[(size_t)(r0 + ty + i) * Cc + c0 + tx];
    __syncthreads();
#pragma unroll
    for (int i = 0; i < 32; i += 8) {
        const float v = t[tx][ty + i];
        const __nv_bfloat16 h = __float2bfloat16(v);
        const size_t o = (size_t)(c0 + ty + i) * R + r0 + tx;
        ohi[o] = h;
        olo[o] = __float2bfloat16(v - __bfloat162float(h));
    }
}

// ---------------------------------------------------------------------------
// Row softmax (in: fp32 scores) -> bf16 hi/lo probability split
// ---------------------------------------------------------------------------
__global__ __launch_bounds__(256)
void softmax_rows(float* __restrict__ scores, __nv_bfloat16* __restrict__ phi,
                  __nv_bfloat16* __restrict__ plo)
{
    __shared__ float red[8];
    const size_t row = blockIdx.x;
    float* p = scores + row * (size_t)SS;
    __nv_bfloat16* oh = phi + row * (size_t)SS;
    __nv_bfloat16* ol = plo + row * (size_t)SS;
    const int tid = threadIdx.x;

    float m = -3.4e38f;
    for (int i = tid; i < SS; i += 256) m = fmaxf(m, p[i]);
#pragma unroll
    for (int o = 16; o; o >>= 1) m = fmaxf(m, __shfl_xor_sync(0xffffffffu, m, o));
    if ((tid & 31) == 0) red[tid >> 5] = m;
    __syncthreads();
    m = -3.4e38f;
#pragma unroll
    for (int i = 0; i < 8; ++i) m = fmaxf(m, red[i]);
    __syncthreads();

    float s = 0.f;
    for (int i = tid; i < SS; i += 256) {
        const float e = __expf(p[i] - m);
        p[i] = e;
        s += e;
    }
#pragma unroll
    for (int o = 16; o; o >>= 1) s += __shfl_xor_sync(0xffffffffu, s, o);
    if ((tid & 31) == 0) red[tid >> 5] = s;
    __syncthreads();
    s = 0.f;
#pragma unroll
    for (int i = 0; i < 8; ++i) s += red[i];
    const float inv = 1.f / s;

    for (int i = tid; i < SS; i += 256) {
        const float v = p[i] * inv;
        const __nv_bfloat16 h = __float2bfloat16(v);
        oh[i] = h;
        ol[i] = __float2bfloat16(v - __bfloat162float(h));
    }
}

// ---------------------------------------------------------------------------
extern "C" void kernel_launch(void* const* d_in, const int* in_sizes, int n_in,
                              void* d_out, int out_size)
{
    const float* h = (const float*)d_in[0];   // [B,S,D]
    const float* W = (const float*)d_in[1];   // [D,D]
    float* out = (float*)d_out;               // [B,S,D]

    __nv_bfloat16 *h_hi, *h_lo, *ht_hi, *ht_lo, *Wt_hi, *Wt_lo, *hW_hi, *hW_lo, *P_hi, *P_lo;
    float* scores;
    cudaGetSymbolAddress((void**)&h_hi, g_h_hi);
    cudaGetSymbolAddress((void**)&h_lo, g_h_lo);
    cudaGetSymbolAddress((void**)&ht_hi, g_ht_hi);
    cudaGetSymbolAddress((void**)&ht_lo, g_ht_lo);
    cudaGetSymbolAddress((void**)&Wt_hi, g_Wt_hi);
    cudaGetSymbolAddress((void**)&Wt_lo, g_Wt_lo);
    cudaGetSymbolAddress((void**)&hW_hi, g_hW_hi);
    cudaGetSymbolAddress((void**)&hW_lo, g_hW_lo);
    cudaGetSymbolAddress((void**)&scores, g_scores);
    cudaGetSymbolAddress((void**)&P_hi, g_P_hi);
    cudaGetSymbolAddress((void**)&P_lo, g_P_lo);

    cudaFuncSetAttribute(gemm_mma<false>, cudaFuncAttributeMaxDynamicSharedMemorySize, GEMM_SMEM);
    cudaFuncSetAttribute(gemm_mma<true>,  cudaFuncAttributeMaxDynamicSharedMemorySize, GEMM_SMEM);

    // pre-passes
    split2<<<8192, 256>>>(h, h_hi, h_lo, (size_t)NB * SS * DD);
    transpose_split<<<dim3(DD / 32, SS / 32, NB), dim3(32, 8)>>>(
        h, ht_hi, ht_lo, SS, DD, (long long)SS * DD, (long long)DD * SS);
    transpose_split<<<dim3(DD / 32, DD / 32, 1), dim3(32, 8)>>>(
        W, Wt_hi, Wt_lo, DD, DD, 0, 0);

    // 1) hW = h @ W : M=16384, N=800, K=800; B = Wt [N,K]; split output
    gemm_mma<true><<<dim3(7, 128, 1), 256, GEMM_SMEM>>>(
        h_hi, h_lo, Wt_hi, Wt_lo, nullptr, hW_hi, hW_lo,
        DD, DD, DD, DD, DD, 0, 0, 0);

    // 2) scores[b] = hW[b] @ h[b]^T : M=N=2048, K=800; fp32 output
    gemm_mma<false><<<dim3(16, 16, NB), 256, GEMM_SMEM>>>(
        hW_hi, hW_lo, h_hi, h_lo, scores, nullptr, nullptr,
        SS, DD, DD, DD, SS,
        (long long)SS * DD, (long long)SS * DD, (long long)SS * SS);

    // 3) softmax + split to bf16 hi/lo
    softmax_rows<<<NB * SS, 256>>>(scores, P_hi, P_lo);

    // 4) out[b] = P[b] @ h[b] : M=2048, N=800, K=2048; B = ht [N,K]; fp32 out
    gemm_mma<false><<<dim3(7, 16, NB), 256, GEMM_SMEM>>>(
        P_hi, P_lo, ht_hi, ht_lo, out, nullptr, nullptr,
        DD, SS, SS, SS, DD,
        (long long)SS * SS, (long long)DD * SS, (long long)SS * DD);
}

// round 14
// speedup vs baseline: 1.0861x; 1.0861x over previous
#include <cuda_runtime.h>
#include <cuda_bf16.h>
#include <cstdint>

#define NB 8
#define SS 2048
#define DD 800

// ---------------------------------------------------------------------------
// Scratch (__device__ globals; no allocations allowed)
// ---------------------------------------------------------------------------
__device__ __nv_bfloat16 g_h_hi [(size_t)NB * SS * DD];
__device__ __nv_bfloat16 g_h_lo [(size_t)NB * SS * DD];
__device__ __nv_bfloat16 g_ht_hi[(size_t)NB * DD * SS];
__device__ __nv_bfloat16 g_ht_lo[(size_t)NB * DD * SS];
__device__ __nv_bfloat16 g_Wt_hi[(size_t)DD * DD];
__device__ __nv_bfloat16 g_Wt_lo[(size_t)DD * DD];
__device__ __nv_bfloat16 g_hW_hi[(size_t)NB * SS * DD];
__device__ __nv_bfloat16 g_hW_lo[(size_t)NB * SS * DD];
__device__ float         g_scores[(size_t)NB * SS * SS];
__device__ __nv_bfloat16 g_P_hi [(size_t)NB * SS * SS];
__device__ __nv_bfloat16 g_P_lo [(size_t)NB * SS * SS];

// ---------------------------------------------------------------------------
// PTX helpers (baseline sm_80+ ops only: cp.async, ldmatrix, mma.sync)
// ---------------------------------------------------------------------------
__device__ __forceinline__ uint32_t smem_u32(const void* p) {
    uint32_t a;
    asm("{ .reg .u64 t; cvta.to.shared.u64 t, %1; cvt.u32.u64 %0, t; }"
        : "=r"(a) : "l"(p));
    return a;
}

__device__ __forceinline__ void cpa16(uint32_t dst, const void* src, uint32_t sz) {
    asm volatile("cp.async.cg.shared.global [%0], [%1], 16, %2;"
                 :: "r"(dst), "l"(src), "r"(sz));
}

__device__ __forceinline__ void ldsm4(uint32_t* r, uint32_t addr) {
    asm volatile("ldmatrix.sync.aligned.m8n8.x4.shared.b16 {%0,%1,%2,%3}, [%4];"
                 : "=r"(r[0]), "=r"(r[1]), "=r"(r[2]), "=r"(r[3]) : "r"(addr));
}

__device__ __forceinline__ void mma16816(float* c, const uint32_t* a, const uint32_t* b) {
    asm volatile(
        "mma.sync.aligned.m16n8k16.row.col.f32.bf16.bf16.f32 "
        "{%0,%1,%2,%3}, {%4,%5,%6,%7}, {%8,%9}, {%0,%1,%2,%3};"
        : "+f"(c[0]), "+f"(c[1]), "+f"(c[2]), "+f"(c[3])
        : "r"(a[0]), "r"(a[1]), "r"(a[2]), "r"(a[3]), "r"(b[0]), "r"(b[1]));
}

// ---------------------------------------------------------------------------
// Split-bf16 NT GEMM: C[M,N] = A[M,K] @ B[N,K]^T (both K-contiguous)
// A ~ Ahi+Alo, B ~ Bhi+Blo; C = AhiBhi + AhiBlo + AloBhi (fp32 accum)
// CTA tile 128x128, BK=32, 8 warps (2x4 grid, 64x32 each), 2-stage cp.async,
// TWO CTAs per SM (independent barriers hide each other's chunk tails).
// (R12 kernel, unchanged — best measured config.)
// ---------------------------------------------------------------------------
static constexpr int LDSB   = 80;            // 32 bf16 padded to 80 bytes
static constexpr int MATB   = 128 * LDSB;    // 10240 B per matrix tile
static constexpr int STAGEB = 4 * MATB;      // Ahi,Alo,Bhi,Blo = 40960 B
static constexpr int GEMM_SMEM = 2 * STAGEB; // 81920 B -> 2 CTAs/SM fit

template <bool SPLIT_OUT>
__global__ __launch_bounds__(256, 2)
void gemm_mma(const __nv_bfloat16* __restrict__ Ahi, const __nv_bfloat16* __restrict__ Alo,
              const __nv_bfloat16* __restrict__ Bhi, const __nv_bfloat16* __restrict__ Blo,
              float* __restrict__ C,
              __nv_bfloat16* __restrict__ Chi, __nv_bfloat16* __restrict__ Clo,
              int N, int K, int lda, int ldb, int ldc,
              long long sA, long long sB, long long sC)
{
    extern __shared__ char smem[];
    const uint32_t sb = smem_u32(smem);
    const int tid = threadIdx.x;
    const int wid = tid >> 5, lane = tid & 31;
    const int wm = wid >> 2, wn = wid & 3;          // 2 x 4 warp grid, 64x32 tiles
    const int mBase = blockIdx.y * 128;
    const int nBase = blockIdx.x * 128;

    Ahi += (long long)blockIdx.z * sA;
    Alo += (long long)blockIdx.z * sA;
    Bhi += (long long)blockIdx.z * sB;
    Blo += (long long)blockIdx.z * sB;
    if (SPLIT_OUT) { Chi += (long long)blockIdx.z * sC; Clo += (long long)blockIdx.z * sC; }
    else           { C   += (long long)blockIdx.z * sC; }

    // A ldsm4: 16 m-rows x k16 per instr
    const uint32_t aOff = (uint32_t)((wm * 64 + (lane & 15)) * LDSB + ((lane >> 4) * 16));
    // B ldsm4: 16 n-rows x k16 per instr (two n8 frags per instr)
    const uint32_t bOff = (uint32_t)((wn * 32 + (((lane >> 4) & 1) << 3) + (lane & 7)) * LDSB
                                     + (((lane >> 3) & 1) * 16));

    float acc[4][4][4];
#pragma unroll
    for (int mt = 0; mt < 4; ++mt)
#pragma unroll
        for (int nt = 0; nt < 4; ++nt)
#pragma unroll
            for (int r = 0; r < 4; ++r) acc[mt][nt][r] = 0.f;

    const int NC = (K + 31) >> 5;

    auto load_chunk = [&](int st, int c) {
        const uint32_t base = sb + (uint32_t)st * STAGEB;
        const int k0 = c * 32;
#pragma unroll
        for (int i = 0; i < 8; ++i) {
            const int u = tid + i * 256;             // 0..2047
            const int mat = u >> 9;                  // 0..3
            const int rem = u & 511;
            const int row = rem >> 2;                // 0..127
            const int kc = rem & 3;                  // 0..3 (16B chunks)
            const uint32_t dst = base + (uint32_t)(mat * MATB + row * LDSB + kc * 16);
            const int k = k0 + kc * 8;
            const bool kok = k < K;
            if (mat < 2) {
                const __nv_bfloat16* src =
                    (mat ? Alo : Ahi) + (size_t)(mBase + row) * lda + (kok ? k : 0);
                cpa16(dst, src, kok ? 16u : 0u);     // src-size 0 -> zero fill
            } else {
                const int nr = nBase + row;
                const bool ok = kok && (nr < N);
                const __nv_bfloat16* src =
                    (mat == 3 ? Blo : Bhi) + (size_t)((nr < N) ? nr : 0) * ldb + (kok ? k : 0);
                cpa16(dst, src, ok ? 16u : 0u);
            }
        }
        asm volatile("cp.async.commit_group;" ::: "memory");
    };

    load_chunk(0, 0);

    for (int c = 0; c < NC; ++c) {
        asm volatile("cp.async.wait_group 0;" ::: "memory");
        __syncthreads();   // all warps done reading the other stage; chunk c landed
        if (c + 1 < NC) load_chunk((c + 1) & 1, c + 1);   // refill freed stage

        const uint32_t base = sb + (uint32_t)(c & 1) * STAGEB;
#pragma unroll
        for (int ks = 0; ks < 2; ++ks) {              // two k=16 steps per chunk
            const uint32_t ksb = (uint32_t)(ks * 32); // byte offset within row
            uint32_t bh[4][2], bl[4][2];
#pragma unroll
            for (int np = 0; np < 2; ++np) {          // each ldsm4 fills two n8 frags
                ldsm4(&bh[np * 2][0], base + 2 * MATB + bOff + (uint32_t)(np * 16 * LDSB) + ksb);
                ldsm4(&bl[np * 2][0], base + 3 * MATB + bOff + (uint32_t)(np * 16 * LDSB) + ksb);
            }
#pragma unroll
            for (int mt = 0; mt < 4; ++mt) {
                uint32_t ah[4], al[4];
                ldsm4(ah, base + aOff + (uint32_t)(mt * 16 * LDSB) + ksb);
                ldsm4(al, base + MATB + aOff + (uint32_t)(mt * 16 * LDSB) + ksb);
#pragma unroll
                for (int nt = 0; nt < 4; ++nt)
                    mma16816(acc[mt][nt], ah, bh[nt]);
#pragma unroll
                for (int nt = 0; nt < 4; ++nt)
                    mma16816(acc[mt][nt], ah, bl[nt]);
#pragma unroll
                for (int nt = 0; nt < 4; ++nt)
                    mma16816(acc[mt][nt], al, bh[nt]);
            }
        }
    }

    // epilogue: direct global stores from register fragments
    const int rowA = mBase + wm * 64 + (lane >> 2);
    const int colA = nBase + wn * 32 + (lane & 3) * 2;
#pragma unroll
    for (int mt = 0; mt < 4; ++mt) {
#pragma unroll
        for (int nt = 0; nt < 4; ++nt) {
            const int col = colA + nt * 8;
            if (col < N) {
#pragma unroll
                for (int half = 0; half < 2; ++half) {
                    const int row = rowA + mt * 16 + half * 8;
                    const float v0 = acc[mt][nt][half * 2 + 0];
                    const float v1 = acc[mt][nt][half * 2 + 1];
                    const size_t off = (size_t)row * ldc + col;
                    if (SPLIT_OUT) {
                        const __nv_bfloat16 h0 = __float2bfloat16(v0);
                        const __nv_bfloat16 h1 = __float2bfloat16(v1);
                        const __nv_bfloat16 l0 = __float2bfloat16(v0 - __bfloat162float(h0));
                        const __nv_bfloat16 l1 = __float2bfloat16(v1 - __bfloat162float(h1));
                        *(__nv_bfloat162*)(Chi + off) = __halves2bfloat162(h0, h1);
                        *(__nv_bfloat162*)(Clo + off) = __halves2bfloat162(l0, l1);
                    } else {
                        *(float2*)(C + off) = make_float2(v0, v1);
                    }
                }
            }
        }
    }
}

// ---------------------------------------------------------------------------
// Transpose fp32 [R,Cc] -> bf16 hi/lo [Cc,R]; optionally ALSO writes the
// non-transposed hi/lo split (fuses the former split2 pass). Batched over z.
// ---------------------------------------------------------------------------
__global__ __launch_bounds__(256)
void transpose_split(const float* __restrict__ in, __nv_bfloat16* __restrict__ ohi,
                     __nv_bfloat16* __restrict__ olo,
                     __nv_bfloat16* __restrict__ fhi,   // may be null
                     __nv_bfloat16* __restrict__ flo,
                     int R, int Cc,
                     long long sIn, long long sOut)
{
    __shared__ float t[32][33];
    in  += (long long)blockIdx.z * sIn;
    ohi += (long long)blockIdx.z * sOut;
    olo += (long long)blockIdx.z * sOut;
    if (fhi) { fhi += (long long)blockIdx.z * sIn; flo += (long long)blockIdx.z * sIn; }
    const int c0 = blockIdx.x * 32, r0 = blockIdx.y * 32;
    const int tx = threadIdx.x, ty = threadIdx.y;   // (32, 8)
#pragma unroll
    for (int i = 0; i < 32; i += 8) {
        const size_t src = (size_t)(r0 + ty + i) * Cc + c0 + tx;
        const float v = in[src];
        t[ty + i][tx] = v;
        if (fhi) {                                   // fused row-major split
            const __nv_bfloat16 h = __float2bfloat16(v);
            fhi[src] = h;
            flo[src] = __float2bfloat16(v - __bfloat162float(h));
        }
    }
    __syncthreads();
#pragma unroll
    for (int i = 0; i < 32; i += 8) {
        const float v = t[tx][ty + i];
        const __nv_bfloat16 h = __float2bfloat16(v);
        const size_t o = (size_t)(c0 + ty + i) * R + r0 + tx;
        ohi[o] = h;
        olo[o] = __float2bfloat16(v - __bfloat162float(h));
    }
}

// ---------------------------------------------------------------------------
// Single-pass row softmax: row (2048 fp32) lives in registers (8/thread).
// Reads scores once, writes bf16 hi/lo probability split once.
// ---------------------------------------------------------------------------
__global__ __launch_bounds__(256)
void softmax_rows(const float* __restrict__ scores, __nv_bfloat16* __restrict__ phi,
                  __nv_bfloat16* __restrict__ plo)
{
    __shared__ float red[8];
    const size_t row = blockIdx.x;
    const float4* p4 = (const float4*)(scores + row * (size_t)SS);
    const int tid = threadIdx.x;

    float4 a = p4[tid];          // cols 4*tid .. 4*tid+3
    float4 b = p4[tid + 256];    // cols 1024+4*tid .. +3
    float v[8] = {a.x, a.y, a.z, a.w, b.x, b.y, b.z, b.w};

    // block max
    float m = v[0];
#pragma unroll
    for (int i = 1; i < 8; ++i) m = fmaxf(m, v[i]);
#pragma unroll
    for (int o = 16; o; o >>= 1) m = fmaxf(m, __shfl_xor_sync(0xffffffffu, m, o));
    if ((tid & 31) == 0) red[tid >> 5] = m;
    __syncthreads();
    m = red[0];
#pragma unroll
    for (int i = 1; i < 8; ++i) m = fmaxf(m, red[i]);
    __syncthreads();

    // exp + block sum (values stay in registers)
    float s = 0.f;
#pragma unroll
    for (int i = 0; i < 8; ++i) {
        v[i] = __expf(v[i] - m);
        s += v[i];
    }
#pragma unroll
    for (int o = 16; o; o >>= 1) s += __shfl_xor_sync(0xffffffffu, s, o);
    if ((tid & 31) == 0) red[tid >> 5] = s;
    __syncthreads();
    s = 0.f;
#pragma unroll
    for (int i = 0; i < 8; ++i) s += red[i];
    const float inv = 1.f / s;

    // write hi/lo split, coalesced bf16x2 stores
    __nv_bfloat16* oh = phi + row * (size_t)SS;
    __nv_bfloat16* ol = plo + row * (size_t)SS;
#pragma unroll
    for (int half = 0; half < 2; ++half) {
        const int base = half * 1024 + tid * 4;
#pragma unroll
        for (int j = 0; j < 2; ++j) {
            const float x0 = v[half * 4 + j * 2 + 0] * inv;
            const float x1 = v[half * 4 + j * 2 + 1] * inv;
            const __nv_bfloat16 h0 = __float2bfloat16(x0);
            const __nv_bfloat16 h1 = __float2bfloat16(x1);
            const __nv_bfloat16 l0 = __float2bfloat16(x0 - __bfloat162float(h0));
            const __nv_bfloat16 l1 = __float2bfloat16(x1 - __bfloat162float(h1));
            *(__nv_bfloat162*)(oh + base + j * 2) = __halves2bfloat162(h0, h1);
            *(__nv_bfloat162*)(ol + base + j * 2) = __halves2bfloat162(l0, l1);
        }
    }
}

// ---------------------------------------------------------------------------
extern "C" void kernel_launch(void* const* d_in, const int* in_sizes, int n_in,
                              void* d_out, int out_size)
{
    const float* h = (const float*)d_in[0];   // [B,S,D]
    const float* W = (const float*)d_in[1];   // [D,D]
    float* out = (float*)d_out;               // [B,S,D]

    __nv_bfloat16 *h_hi, *h_lo, *ht_hi, *ht_lo, *Wt_hi, *Wt_lo, *hW_hi, *hW_lo, *P_hi, *P_lo;
    float* scores;
    cudaGetSymbolAddress((void**)&h_hi, g_h_hi);
    cudaGetSymbolAddress((void**)&h_lo, g_h_lo);
    cudaGetSymbolAddress((void**)&ht_hi, g_ht_hi);
    cudaGetSymbolAddress((void**)&ht_lo, g_ht_lo);
    cudaGetSymbolAddress((void**)&Wt_hi, g_Wt_hi);
    cudaGetSymbolAddress((void**)&Wt_lo, g_Wt_lo);
    cudaGetSymbolAddress((void**)&hW_hi, g_hW_hi);
    cudaGetSymbolAddress((void**)&hW_lo, g_hW_lo);
    cudaGetSymbolAddress((void**)&scores, g_scores);
    cudaGetSymbolAddress((void**)&P_hi, g_P_hi);
    cudaGetSymbolAddress((void**)&P_lo, g_P_lo);

    cudaFuncSetAttribute(gemm_mma<false>, cudaFuncAttributeMaxDynamicSharedMemorySize, GEMM_SMEM);
    cudaFuncSetAttribute(gemm_mma<true>,  cudaFuncAttributeMaxDynamicSharedMemorySize, GEMM_SMEM);

    // pre-passes: h transpose + fused row-major split; W transpose
    transpose_split<<<dim3(DD / 32, SS / 32, NB), dim3(32, 8)>>>(
        h, ht_hi, ht_lo, h_hi, h_lo, SS, DD, (long long)SS * DD, (long long)DD * SS);
    transpose_split<<<dim3(DD / 32, DD / 32, 1), dim3(32, 8)>>>(
        W, Wt_hi, Wt_lo, nullptr, nullptr, DD, DD, 0, 0);

    // 1) hW = h @ W : M=16384, N=800, K=800; B = Wt [N,K]; split output
    gemm_mma<true><<<dim3(7, 128, 1), 256, GEMM_SMEM>>>(
        h_hi, h_lo, Wt_hi, Wt_lo, nullptr, hW_hi, hW_lo,
        DD, DD, DD, DD, DD, 0, 0, 0);

    // 2) scores[b] = hW[b] @ h[b]^T : M=N=2048, K=800; fp32 output
    gemm_mma<false><<<dim3(16, 16, NB), 256, GEMM_SMEM>>>(
        hW_hi, hW_lo, h_hi, h_lo, scores, nullptr, nullptr,
        SS, DD, DD, DD, SS,
        (long long)SS * DD, (long long)SS * DD, (long long)SS * SS);

    // 3) single-pass softmax + bf16 hi/lo split
    softmax_rows<<<NB * SS, 256>>>(scores, P_hi, P_lo);

    // 4) out[b] = P[b] @ h[b] : M=2048, N=800, K=2048; B = ht [N,K]; fp32 out
    gemm_mma<false><<<dim3(7, 16, NB), 256, GEMM_SMEM>>>(
        P_hi, P_lo, ht_hi, ht_lo, out, nullptr, nullptr,
        DD, SS, SS, SS, DD,
        (long long)SS * SS, (long long)DD * SS, (long long)SS * DD);
}

// round 15
// speedup vs baseline: 1.1121x; 1.0239x over previous
#include <cuda_runtime.h>
#include <cuda_bf16.h>
#include <cstdint>

#define NB 8
#define SS 2048
#define DD 800

// ---------------------------------------------------------------------------
// Scratch (__device__ globals; no allocations allowed)
// ---------------------------------------------------------------------------
__device__ __nv_bfloat16 g_h_hi [(size_t)NB * SS * DD];
__device__ __nv_bfloat16 g_h_lo [(size_t)NB * SS * DD];
__device__ __nv_bfloat16 g_ht_hi[(size_t)NB * DD * SS];
__device__ __nv_bfloat16 g_ht_lo[(size_t)NB * DD * SS];
__device__ __nv_bfloat16 g_Wt_hi[(size_t)DD * DD];
__device__ __nv_bfloat16 g_Wt_lo[(size_t)DD * DD];
__device__ __nv_bfloat16 g_hW_hi[(size_t)NB * SS * DD];
__device__ __nv_bfloat16 g_hW_lo[(size_t)NB * SS * DD];
__device__ float         g_scores[(size_t)NB * SS * SS];
__device__ __nv_bfloat16 g_P_hi [(size_t)NB * SS * SS];
__device__ __nv_bfloat16 g_P_lo [(size_t)NB * SS * SS];

// ---------------------------------------------------------------------------
// PTX helpers (baseline sm_80+ ops only: cp.async, ldmatrix, mma.sync)
// ---------------------------------------------------------------------------
__device__ __forceinline__ uint32_t smem_u32(const void* p) {
    uint32_t a;
    asm("{ .reg .u64 t; cvta.to.shared.u64 t, %1; cvt.u32.u64 %0, t; }"
        : "=r"(a) : "l"(p));
    return a;
}

__device__ __forceinline__ void cpa16(uint32_t dst, const void* src, uint32_t sz) {
    asm volatile("cp.async.cg.shared.global [%0], [%1], 16, %2;"
                 :: "r"(dst), "l"(src), "r"(sz));
}

__device__ __forceinline__ void ldsm4(uint32_t* r, uint32_t addr) {
    asm volatile("ldmatrix.sync.aligned.m8n8.x4.shared.b16 {%0,%1,%2,%3}, [%4];"
                 : "=r"(r[0]), "=r"(r[1]), "=r"(r[2]), "=r"(r[3]) : "r"(addr));
}

__device__ __forceinline__ void mma16816(float* c, const uint32_t* a, const uint32_t* b) {
    asm volatile(
        "mma.sync.aligned.m16n8k16.row.col.f32.bf16.bf16.f32 "
        "{%0,%1,%2,%3}, {%4,%5,%6,%7}, {%8,%9}, {%0,%1,%2,%3};"
        : "+f"(c[0]), "+f"(c[1]), "+f"(c[2]), "+f"(c[3])
        : "r"(a[0]), "r"(a[1]), "r"(a[2]), "r"(a[3]), "r"(b[0]), "r"(b[1]));
}

// ---------------------------------------------------------------------------
// Split-bf16 NT GEMM: C[M,N] = A[M,K] @ B[N,K]^T (both K-contiguous)
// A ~ Ahi+Alo, B ~ Bhi+Blo; C = AhiBhi + AhiBlo + AloBhi (fp32 accum)
// CTA tile 128x128, BK=32, 8 warps (2x4 grid, 64x32 each), 2-stage cp.async,
// TWO CTAs per SM. NEW: the two warps sharing an SMSP (wm=0 / wm=1) process
// the chunk's two k16-steps in opposite order, anti-phasing their LDSM
// bursts so one warp's MMAs cover the other's fragment loads.
// ---------------------------------------------------------------------------
static constexpr int LDSB   = 80;            // 32 bf16 padded to 80 bytes
static constexpr int MATB   = 128 * LDSB;    // 10240 B per matrix tile
static constexpr int STAGEB = 4 * MATB;      // Ahi,Alo,Bhi,Blo = 40960 B
static constexpr int GEMM_SMEM = 2 * STAGEB; // 81920 B -> 2 CTAs/SM fit

template <bool SPLIT_OUT>
__global__ __launch_bounds__(256, 2)
void gemm_mma(const __nv_bfloat16* __restrict__ Ahi, const __nv_bfloat16* __restrict__ Alo,
              const __nv_bfloat16* __restrict__ Bhi, const __nv_bfloat16* __restrict__ Blo,
              float* __restrict__ C,
              __nv_bfloat16* __restrict__ Chi, __nv_bfloat16* __restrict__ Clo,
              int N, int K, int lda, int ldb, int ldc,
              long long sA, long long sB, long long sC)
{
    extern __shared__ char smem[];
    const uint32_t sb = smem_u32(smem);
    const int tid = threadIdx.x;
    const int wid = tid >> 5, lane = tid & 31;
    const int wm = wid >> 2, wn = wid & 3;          // 2 x 4 warp grid, 64x32 tiles
    const int mBase = blockIdx.y * 128;
    const int nBase = blockIdx.x * 128;

    Ahi += (long long)blockIdx.z * sA;
    Alo += (long long)blockIdx.z * sA;
    Bhi += (long long)blockIdx.z * sB;
    Blo += (long long)blockIdx.z * sB;
    if (SPLIT_OUT) { Chi += (long long)blockIdx.z * sC; Clo += (long long)blockIdx.z * sC; }
    else           { C   += (long long)blockIdx.z * sC; }

    // A ldsm4: 16 m-rows x k16 per instr
    const uint32_t aOff = (uint32_t)((wm * 64 + (lane & 15)) * LDSB + ((lane >> 4) * 16));
    // B ldsm4: 16 n-rows x k16 per instr (two n8 frags per instr)
    const uint32_t bOff = (uint32_t)((wn * 32 + (((lane >> 4) & 1) << 3) + (lane & 7)) * LDSB
                                     + (((lane >> 3) & 1) * 16));

    float acc[4][4][4];
#pragma unroll
    for (int mt = 0; mt < 4; ++mt)
#pragma unroll
        for (int nt = 0; nt < 4; ++nt)
#pragma unroll
            for (int r = 0; r < 4; ++r) acc[mt][nt][r] = 0.f;

    const int NC = (K + 31) >> 5;

    auto load_chunk = [&](int st, int c) {
        const uint32_t base = sb + (uint32_t)st * STAGEB;
        const int k0 = c * 32;
#pragma unroll
        for (int i = 0; i < 8; ++i) {
            const int u = tid + i * 256;             // 0..2047
            const int mat = u >> 9;                  // 0..3
            const int rem = u & 511;
            const int row = rem >> 2;                // 0..127
            const int kc = rem & 3;                  // 0..3 (16B chunks)
            const uint32_t dst = base + (uint32_t)(mat * MATB + row * LDSB + kc * 16);
            const int k = k0 + kc * 8;
            const bool kok = k < K;
            if (mat < 2) {
                const __nv_bfloat16* src =
                    (mat ? Alo : Ahi) + (size_t)(mBase + row) * lda + (kok ? k : 0);
                cpa16(dst, src, kok ? 16u : 0u);     // src-size 0 -> zero fill
            } else {
                const int nr = nBase + row;
                const bool ok = kok && (nr < N);
                const __nv_bfloat16* src =
                    (mat == 3 ? Blo : Bhi) + (size_t)((nr < N) ? nr : 0) * ldb + (kok ? k : 0);
                cpa16(dst, src, ok ? 16u : 0u);
            }
        }
        asm volatile("cp.async.commit_group;" ::: "memory");
    };

    load_chunk(0, 0);

    for (int c = 0; c < NC; ++c) {
        asm volatile("cp.async.wait_group 0;" ::: "memory");
        __syncthreads();   // all warps done reading the other stage; chunk c landed
        if (c + 1 < NC) load_chunk((c + 1) & 1, c + 1);   // refill freed stage

        const uint32_t base = sb + (uint32_t)(c & 1) * STAGEB;
#pragma unroll
        for (int ks = 0; ks < 2; ++ks) {              // two k=16 steps per chunk
            const int kk = ks ^ wm;                   // SMSP warp pair anti-phase
            const uint32_t ksb = (uint32_t)(kk * 32); // byte offset within row
            uint32_t bh[4][2], bl[4][2];
#pragma unroll
            for (int np = 0; np < 2; ++np) {          // each ldsm4 fills two n8 frags
                ldsm4(&bh[np * 2][0], base + 2 * MATB + bOff + (uint32_t)(np * 16 * LDSB) + ksb);
                ldsm4(&bl[np * 2][0], base + 3 * MATB + bOff + (uint32_t)(np * 16 * LDSB) + ksb);
            }
#pragma unroll
            for (int mt = 0; mt < 4; ++mt) {
                uint32_t ah[4], al[4];
                ldsm4(ah, base + aOff + (uint32_t)(mt * 16 * LDSB) + ksb);
                ldsm4(al, base + MATB + aOff + (uint32_t)(mt * 16 * LDSB) + ksb);
#pragma unroll
                for (int nt = 0; nt < 4; ++nt)
                    mma16816(acc[mt][nt], ah, bh[nt]);
#pragma unroll
                for (int nt = 0; nt < 4; ++nt)
                    mma16816(acc[mt][nt], ah, bl[nt]);
#pragma unroll
                for (int nt = 0; nt < 4; ++nt)
                    mma16816(acc[mt][nt], al, bh[nt]);
            }
        }
    }

    // epilogue: direct global stores from register fragments
    const int rowA = mBase + wm * 64 + (lane >> 2);
    const int colA = nBase + wn * 32 + (lane & 3) * 2;
#pragma unroll
    for (int mt = 0; mt < 4; ++mt) {
#pragma unroll
        for (int nt = 0; nt < 4; ++nt) {
            const int col = colA + nt * 8;
            if (col < N) {
#pragma unroll
                for (int half = 0; half < 2; ++half) {
                    const int row = rowA + mt * 16 + half * 8;
                    const float v0 = acc[mt][nt][half * 2 + 0];
                    const float v1 = acc[mt][nt][half * 2 + 1];
                    const size_t off = (size_t)row * ldc + col;
                    if (SPLIT_OUT) {
                        const __nv_bfloat16 h0 = __float2bfloat16(v0);
                        const __nv_bfloat16 h1 = __float2bfloat16(v1);
                        const __nv_bfloat16 l0 = __float2bfloat16(v0 - __bfloat162float(h0));
                        const __nv_bfloat16 l1 = __float2bfloat16(v1 - __bfloat162float(h1));
                        *(__nv_bfloat162*)(Chi + off) = __halves2bfloat162(h0, h1);
                        *(__nv_bfloat162*)(Clo + off) = __halves2bfloat162(l0, l1);
                    } else {
                        *(float2*)(C + off) = make_float2(v0, v1);
                    }
                }
            }
        }
    }
}

// ---------------------------------------------------------------------------
// Transpose fp32 [R,Cc] -> bf16 hi/lo [Cc,R]; optionally ALSO writes the
// non-transposed hi/lo split (fuses the former split2 pass). Batched over z.
// ---------------------------------------------------------------------------
__global__ __launch_bounds__(256)
void transpose_split(const float* __restrict__ in, __nv_bfloat16* __restrict__ ohi,
                     __nv_bfloat16* __restrict__ olo,
                     __nv_bfloat16* __restrict__ fhi,   // may be null
                     __nv_bfloat16* __restrict__ flo,
                     int R, int Cc,
                     long long sIn, long long sOut)
{
    __shared__ float t[32][33];
    in  += (long long)blockIdx.z * sIn;
    ohi += (long long)blockIdx.z * sOut;
    olo += (long long)blockIdx.z * sOut;
    if (fhi) { fhi += (long long)blockIdx.z * sIn; flo += (long long)blockIdx.z * sIn; }
    const int c0 = blockIdx.x * 32, r0 = blockIdx.y * 32;
    const int tx = threadIdx.x, ty = threadIdx.y;   // (32, 8)
#pragma unroll
    for (int i = 0; i < 32; i += 8) {
        const size_t src = (size_t)(r0 + ty + i) * Cc + c0 + tx;
        const float v = in[src];
        t[ty + i][tx] = v;
        if (fhi) {                                   // fused row-major split
            const __nv_bfloat16 h = __float2bfloat16(v);
            fhi[src] = h;
            flo[src] = __float2bfloat16(v - __bfloat162float(h));
        }
    }
    __syncthreads();
#pragma unroll
    for (int i = 0; i < 32; i += 8) {
        const float v = t[tx][ty + i];
        const __nv_bfloat16 h = __float2bfloat16(v);
        const size_t o = (size_t)(c0 + ty + i) * R + r0 + tx;
        ohi[o] = h;
        olo[o] = __float2bfloat16(v - __bfloat162float(h));
    }
}

// ---------------------------------------------------------------------------
// Single-pass row softmax: row (2048 fp32) lives in registers (8/thread).
// Reads scores once, writes bf16 hi/lo probability split once.
// ---------------------------------------------------------------------------
__global__ __launch_bounds__(256)
void softmax_rows(const float* __restrict__ scores, __nv_bfloat16* __restrict__ phi,
                  __nv_bfloat16* __restrict__ plo)
{
    __shared__ float red[8];
    const size_t row = blockIdx.x;
    const float4* p4 = (const float4*)(scores + row * (size_t)SS);
    const int tid = threadIdx.x;

    float4 a = p4[tid];          // cols 4*tid .. 4*tid+3
    float4 b = p4[tid + 256];    // cols 1024+4*tid .. +3
    float v[8] = {a.x, a.y, a.z, a.w, b.x, b.y, b.z, b.w};

    // block max
    float m = v[0];
#pragma unroll
    for (int i = 1; i < 8; ++i) m = fmaxf(m, v[i]);
#pragma unroll
    for (int o = 16; o; o >>= 1) m = fmaxf(m, __shfl_xor_sync(0xffffffffu, m, o));
    if ((tid & 31) == 0) red[tid >> 5] = m;
    __syncthreads();
    m = red[0];
#pragma unroll
    for (int i = 1; i < 8; ++i) m = fmaxf(m, red[i]);
    __syncthreads();

    // exp + block sum (values stay in registers)
    float s = 0.f;
#pragma unroll
    for (int i = 0; i < 8; ++i) {
        v[i] = __expf(v[i] - m);
        s += v[i];
    }
#pragma unroll
    for (int o = 16; o; o >>= 1) s += __shfl_xor_sync(0xffffffffu, s, o);
    if ((tid & 31) == 0) red[tid >> 5] = s;
    __syncthreads();
    s = 0.f;
#pragma unroll
    for (int i = 0; i < 8; ++i) s += red[i];
    const float inv = 1.f / s;

    // write hi/lo split, coalesced bf16x2 stores
    __nv_bfloat16* oh = phi + row * (size_t)SS;
    __nv_bfloat16* ol = plo + row * (size_t)SS;
#pragma unroll
    for (int half = 0; half < 2; ++half) {
        const int base = half * 1024 + tid * 4;
#pragma unroll
        for (int j = 0; j < 2; ++j) {
            const float x0 = v[half * 4 + j * 2 + 0] * inv;
            const float x1 = v[half * 4 + j * 2 + 1] * inv;
            const __nv_bfloat16 h0 = __float2bfloat16(x0);
            const __nv_bfloat16 h1 = __float2bfloat16(x1);
            const __nv_bfloat16 l0 = __float2bfloat16(x0 - __bfloat162float(h0));
            const __nv_bfloat16 l1 = __float2bfloat16(x1 - __bfloat162float(h1));
            *(__nv_bfloat162*)(oh + base + j * 2) = __halves2bfloat162(h0, h1);
            *(__nv_bfloat162*)(ol + base + j * 2) = __halves2bfloat162(l0, l1);
        }
    }
}

// ---------------------------------------------------------------------------
extern "C" void kernel_launch(void* const* d_in, const int* in_sizes, int n_in,
                              void* d_out, int out_size)
{
    const float* h = (const float*)d_in[0];   // [B,S,D]
    const float* W = (const float*)d_in[1];   // [D,D]
    float* out = (float*)d_out;               // [B,S,D]

    __nv_bfloat16 *h_hi, *h_lo, *ht_hi, *ht_lo, *Wt_hi, *Wt_lo, *hW_hi, *hW_lo, *P_hi, *P_lo;
    float* scores;
    cudaGetSymbolAddress((void**)&h_hi, g_h_hi);
    cudaGetSymbolAddress((void**)&h_lo, g_h_lo);
    cudaGetSymbolAddress((void**)&ht_hi, g_ht_hi);
    cudaGetSymbolAddress((void**)&ht_lo, g_ht_lo);
    cudaGetSymbolAddress((void**)&Wt_hi, g_Wt_hi);
    cudaGetSymbolAddress((void**)&Wt_lo, g_Wt_lo);
    cudaGetSymbolAddress((void**)&hW_hi, g_hW_hi);
    cudaGetSymbolAddress((void**)&hW_lo, g_hW_lo);
    cudaGetSymbolAddress((void**)&scores, g_scores);
    cudaGetSymbolAddress((void**)&P_hi, g_P_hi);
    cudaGetSymbolAddress((void**)&P_lo, g_P_lo);

    cudaFuncSetAttribute(gemm_mma<false>, cudaFuncAttributeMaxDynamicSharedMemorySize, GEMM_SMEM);
    cudaFuncSetAttribute(gemm_mma<true>,  cudaFuncAttributeMaxDynamicSharedMemorySize, GEMM_SMEM);

    // pre-passes: h transpose + fused row-major split; W transpose
    transpose_split<<<dim3(DD / 32, SS / 32, NB), dim3(32, 8)>>>(
        h, ht_hi, ht_lo, h_hi, h_lo, SS, DD, (long long)SS * DD, (long long)DD * SS);
    transpose_split<<<dim3(DD / 32, DD / 32, 1), dim3(32, 8)>>>(
        W, Wt_hi, Wt_lo, nullptr, nullptr, DD, DD, 0, 0);

    // 1) hW = h @ W : M=16384, N=800, K=800; B = Wt [N,K]; split output
    gemm_mma<true><<<dim3(7, 128, 1), 256, GEMM_SMEM>>>(
        h_hi, h_lo, Wt_hi, Wt_lo, nullptr, hW_hi, hW_lo,
        DD, DD, DD, DD, DD, 0, 0, 0);

    // 2) scores[b] = hW[b] @ h[b]^T : M=N=2048, K=800; fp32 output
    gemm_mma<false><<<dim3(16, 16, NB), 256, GEMM_SMEM>>>(
        hW_hi, hW_lo, h_hi, h_lo, scores, nullptr, nullptr,
        SS, DD, DD, DD, SS,
        (long long)SS * DD, (long long)SS * DD, (long long)SS * SS);

    // 3) single-pass softmax + bf16 hi/lo split
    softmax_rows<<<NB * SS, 256>>>(scores, P_hi, P_lo);

    // 4) out[b] = P[b] @ h[b] : M=2048, N=800, K=2048; B = ht [N,K]; fp32 out
    gemm_mma<false><<<dim3(7, 16, NB), 256, GEMM_SMEM>>>(
        P_hi, P_lo, ht_hi, ht_lo, out, nullptr, nullptr,
        DD, SS, SS, SS, DD,
        (long long)SS * SS, (long long)DD * SS, (long long)SS * DD);
}

// round 16
// speedup vs baseline: 1.1757x; 1.0572x over previous
#include <cuda_runtime.h>
#include <cuda_bf16.h>
#include <cstdint>

#define NB 8
#define SS 2048
#define DD 800

// ---------------------------------------------------------------------------
// Scratch (__device__ globals; no allocations allowed)
// ---------------------------------------------------------------------------
__device__ __nv_bfloat16 g_h_hi [(size_t)NB * SS * DD];
__device__ __nv_bfloat16 g_h_lo [(size_t)NB * SS * DD];
__device__ __nv_bfloat16 g_ht_hi[(size_t)NB * DD * SS];
__device__ __nv_bfloat16 g_ht_lo[(size_t)NB * DD * SS];
__device__ __nv_bfloat16 g_Wt_hi[(size_t)DD * DD];
__device__ __nv_bfloat16 g_Wt_lo[(size_t)DD * DD];
__device__ __nv_bfloat16 g_hW_hi[(size_t)NB * SS * DD];
__device__ __nv_bfloat16 g_hW_lo[(size_t)NB * SS * DD];
__device__ float         g_scores[(size_t)NB * SS * SS];
__device__ __nv_bfloat16 g_P_hi [(size_t)NB * SS * SS];
__device__ __nv_bfloat16 g_P_lo [(size_t)NB * SS * SS];

// ---------------------------------------------------------------------------
// PTX helpers (baseline sm_80+ ops only: cp.async, ldmatrix, mma.sync)
// ---------------------------------------------------------------------------
__device__ __forceinline__ uint32_t smem_u32(const void* p) {
    uint32_t a;
    asm("{ .reg .u64 t; cvta.to.shared.u64 t, %1; cvt.u32.u64 %0, t; }"
        : "=r"(a) : "l"(p));
    return a;
}

__device__ __forceinline__ void cpa16(uint32_t dst, const void* src, uint32_t sz) {
    asm volatile("cp.async.cg.shared.global [%0], [%1], 16, %2;"
                 :: "r"(dst), "l"(src), "r"(sz));
}

__device__ __forceinline__ void ldsm4(uint32_t* r, uint32_t addr) {
    asm volatile("ldmatrix.sync.aligned.m8n8.x4.shared.b16 {%0,%1,%2,%3}, [%4];"
                 : "=r"(r[0]), "=r"(r[1]), "=r"(r[2]), "=r"(r[3]) : "r"(addr));
}

__device__ __forceinline__ void mma16816(float* c, const uint32_t* a, const uint32_t* b) {
    asm volatile(
        "mma.sync.aligned.m16n8k16.row.col.f32.bf16.bf16.f32 "
        "{%0,%1,%2,%3}, {%4,%5,%6,%7}, {%8,%9}, {%0,%1,%2,%3};"
        : "+f"(c[0]), "+f"(c[1]), "+f"(c[2]), "+f"(c[3])
        : "r"(a[0]), "r"(a[1]), "r"(a[2]), "r"(a[3]), "r"(b[0]), "r"(b[1]));
}

// ---------------------------------------------------------------------------
// Split-bf16 NT GEMM: C[M,N] = A[M,K] @ B[N,K]^T (both K-contiguous)
// A ~ Ahi+Alo, B ~ Bhi+Blo; C = AhiBhi + AhiBlo + AloBhi (fp32 accum)
// CTA tile 128xBN (BN=128: 8 warps/2 CTAs per SM; BN=64: 4 warps/3 CTAs),
// warp tile always 64x32; BK=32, 2-stage cp.async; SMSP warp pairs process
// k16-steps in opposite order (anti-phase LDSM bursts).
// ---------------------------------------------------------------------------
static constexpr int LDSB  = 80;             // 32 bf16 padded to 80 bytes
static constexpr int AMATB = 128 * LDSB;     // 10240 B (A hi or lo)

template <int BN> struct GemmCfg {
    static constexpr int THREADS = BN * 2;               // 256 / 128
    static constexpr int BMATB   = BN * LDSB;
    static constexpr int STAGEB  = 2 * AMATB + 2 * BMATB;
    static constexpr int SMEM    = 2 * STAGEB;
    static constexpr int OCC     = (BN == 128) ? 2 : 3;
};

template <bool SPLIT_OUT, int BN>
__global__ __launch_bounds__(GemmCfg<BN>::THREADS, GemmCfg<BN>::OCC)
void gemm_mma(const __nv_bfloat16* __restrict__ Ahi, const __nv_bfloat16* __restrict__ Alo,
              const __nv_bfloat16* __restrict__ Bhi, const __nv_bfloat16* __restrict__ Blo,
              float* __restrict__ C,
              __nv_bfloat16* __restrict__ Chi, __nv_bfloat16* __restrict__ Clo,
              int N, int K, int lda, int ldb, int ldc,
              long long sA, long long sB, long long sC)
{
    using CFG = GemmCfg<BN>;
    constexpr int THREADS = CFG::THREADS;
    constexpr int BMATB = CFG::BMATB;
    constexpr int STAGEB = CFG::STAGEB;
    constexpr int WN = BN / 32;                 // warp-grid width (4 or 2)

    extern __shared__ char smem[];
    const uint32_t sb = smem_u32(smem);
    const int tid = threadIdx.x;
    const int wid = tid >> 5, lane = tid & 31;
    const int wm = wid / WN, wn = wid % WN;     // 2 x WN warp grid, 64x32 tiles
    const int mBase = blockIdx.y * 128;
    const int nBase = blockIdx.x * BN;

    Ahi += (long long)blockIdx.z * sA;
    Alo += (long long)blockIdx.z * sA;
    Bhi += (long long)blockIdx.z * sB;
    Blo += (long long)blockIdx.z * sB;
    if (SPLIT_OUT) { Chi += (long long)blockIdx.z * sC; Clo += (long long)blockIdx.z * sC; }
    else           { C   += (long long)blockIdx.z * sC; }

    // A ldsm4: 16 m-rows x k16 per instr
    const uint32_t aOff = (uint32_t)((wm * 64 + (lane & 15)) * LDSB + ((lane >> 4) * 16));
    // B ldsm4: 16 n-rows x k16 per instr (two n8 frags per instr)
    const uint32_t bOff = (uint32_t)((wn * 32 + (((lane >> 4) & 1) << 3) + (lane & 7)) * LDSB
                                     + (((lane >> 3) & 1) * 16));

    float acc[4][4][4];
#pragma unroll
    for (int mt = 0; mt < 4; ++mt)
#pragma unroll
        for (int nt = 0; nt < 4; ++nt)
#pragma unroll
            for (int r = 0; r < 4; ++r) acc[mt][nt][r] = 0.f;

    const int NC = (K + 31) >> 5;

    auto load_chunk = [&](int st, int c) {
        const uint32_t base = sb + (uint32_t)st * STAGEB;
        const int k0 = c * 32;
        constexpr int TOT = 1024 + 8 * BN;      // 16B units per chunk
        constexpr int PER = TOT / THREADS;      // 8 (BN=128) / 12 (BN=64)
#pragma unroll
        for (int i = 0; i < PER; ++i) {
            const int u = tid + i * THREADS;
            if (u < 1024) {                     // A: 2 mats x 128 rows x 4 kc
                const int mat = u >> 9;
                const int rem = u & 511;
                const int row = rem >> 2;
                const int kc = rem & 3;
                const uint32_t dst = base + (uint32_t)(mat * AMATB + row * LDSB + kc * 16);
                const int k = k0 + kc * 8;
                const bool kok = k < K;
                const __nv_bfloat16* src =
                    (mat ? Alo : Ahi) + (size_t)(mBase + row) * lda + (kok ? k : 0);
                cpa16(dst, src, kok ? 16u : 0u);  // src-size 0 -> zero fill
            } else {                            // B: 2 mats x BN rows x 4 kc
                const int v = u - 1024;
                const int mat = v / (4 * BN);
                const int rem = v - mat * (4 * BN);
                const int row = rem >> 2;
                const int kc = rem & 3;
                const uint32_t dst = base + (uint32_t)(2 * AMATB + mat * BMATB
                                                       + row * LDSB + kc * 16);
                const int k = k0 + kc * 8;
                const int nr = nBase + row;
                const bool ok = (k < K) && (nr < N);
                const __nv_bfloat16* src =
                    (mat ? Blo : Bhi) + (size_t)((nr < N) ? nr : 0) * ldb + ((k < K) ? k : 0);
                cpa16(dst, src, ok ? 16u : 0u);
            }
        }
        asm volatile("cp.async.commit_group;" ::: "memory");
    };

    load_chunk(0, 0);

    for (int c = 0; c < NC; ++c) {
        asm volatile("cp.async.wait_group 0;" ::: "memory");
        __syncthreads();   // all warps done reading the other stage; chunk c landed
        if (c + 1 < NC) load_chunk((c + 1) & 1, c + 1);   // refill freed stage

        const uint32_t base = sb + (uint32_t)(c & 1) * STAGEB;
#pragma unroll
        for (int ks = 0; ks < 2; ++ks) {              // two k=16 steps per chunk
            const int kk = ks ^ wm;                   // SMSP warp pair anti-phase
            const uint32_t ksb = (uint32_t)(kk * 32); // byte offset within row
            uint32_t bh[4][2], bl[4][2];
#pragma unroll
            for (int np = 0; np < 2; ++np) {          // each ldsm4 fills two n8 frags
                ldsm4(&bh[np * 2][0], base + 2 * AMATB + bOff + (uint32_t)(np * 16 * LDSB) + ksb);
                ldsm4(&bl[np * 2][0], base + 2 * AMATB + BMATB + bOff
                                      + (uint32_t)(np * 16 * LDSB) + ksb);
            }
#pragma unroll
            for (int mt = 0; mt < 4; ++mt) {
                uint32_t ah[4], al[4];
                ldsm4(ah, base + aOff + (uint32_t)(mt * 16 * LDSB) + ksb);
                ldsm4(al, base + AMATB + aOff + (uint32_t)(mt * 16 * LDSB) + ksb);
#pragma unroll
                for (int nt = 0; nt < 4; ++nt)
                    mma16816(acc[mt][nt], ah, bh[nt]);
#pragma unroll
                for (int nt = 0; nt < 4; ++nt)
                    mma16816(acc[mt][nt], ah, bl[nt]);
#pragma unroll
                for (int nt = 0; nt < 4; ++nt)
                    mma16816(acc[mt][nt], al, bh[nt]);
            }
        }
    }

    // epilogue: direct global stores from register fragments
    const int rowA = mBase + wm * 64 + (lane >> 2);
    const int colA = nBase + wn * 32 + (lane & 3) * 2;
#pragma unroll
    for (int mt = 0; mt < 4; ++mt) {
#pragma unroll
        for (int nt = 0; nt < 4; ++nt) {
            const int col = colA + nt * 8;
            if (col < N) {
#pragma unroll
                for (int half = 0; half < 2; ++half) {
                    const int row = rowA + mt * 16 + half * 8;
                    const float v0 = acc[mt][nt][half * 2 + 0];
                    const float v1 = acc[mt][nt][half * 2 + 1];
                    const size_t off = (size_t)row * ldc + col;
                    if (SPLIT_OUT) {
                        const __nv_bfloat16 h0 = __float2bfloat16(v0);
                        const __nv_bfloat16 h1 = __float2bfloat16(v1);
                        const __nv_bfloat16 l0 = __float2bfloat16(v0 - __bfloat162float(h0));
                        const __nv_bfloat16 l1 = __float2bfloat16(v1 - __bfloat162float(h1));
                        *(__nv_bfloat162*)(Chi + off) = __halves2bfloat162(h0, h1);
                        *(__nv_bfloat162*)(Clo + off) = __halves2bfloat162(l0, l1);
                    } else {
                        *(float2*)(C + off) = make_float2(v0, v1);
                    }
                }
            }
        }
    }
}

// ---------------------------------------------------------------------------
// Transpose fp32 [R,Cc] -> bf16 hi/lo [Cc,R]; optionally ALSO writes the
// non-transposed hi/lo split (fuses the former split2 pass). Batched over z.
// ---------------------------------------------------------------------------
__global__ __launch_bounds__(256)
void transpose_split(const float* __restrict__ in, __nv_bfloat16* __restrict__ ohi,
                     __nv_bfloat16* __restrict__ olo,
                     __nv_bfloat16* __restrict__ fhi,   // may be null
                     __nv_bfloat16* __restrict__ flo,
                     int R, int Cc,
                     long long sIn, long long sOut)
{
    __shared__ float t[32][33];
    in  += (long long)blockIdx.z * sIn;
    ohi += (long long)blockIdx.z * sOut;
    olo += (long long)blockIdx.z * sOut;
    if (fhi) { fhi += (long long)blockIdx.z * sIn; flo += (long long)blockIdx.z * sIn; }
    const int c0 = blockIdx.x * 32, r0 = blockIdx.y * 32;
    const int tx = threadIdx.x, ty = threadIdx.y;   // (32, 8)
#pragma unroll
    for (int i = 0; i < 32; i += 8) {
        const size_t src = (size_t)(r0 + ty + i) * Cc + c0 + tx;
        const float v = in[src];
        t[ty + i][tx] = v;
        if (fhi) {                                   // fused row-major split
            const __nv_bfloat16 h = __float2bfloat16(v);
            fhi[src] = h;
            flo[src] = __float2bfloat16(v - __bfloat162float(h));
        }
    }
    __syncthreads();
#pragma unroll
    for (int i = 0; i < 32; i += 8) {
        const float v = t[tx][ty + i];
        const __nv_bfloat16 h = __float2bfloat16(v);
        const size_t o = (size_t)(c0 + ty + i) * R + r0 + tx;
        ohi[o] = h;
        olo[o] = __float2bfloat16(v - __bfloat162float(h));
    }
}

// ---------------------------------------------------------------------------
// Single-pass row softmax: row (2048 fp32) lives in registers (8/thread).
// Reads scores once, writes bf16 hi/lo probability split once.
// ---------------------------------------------------------------------------
__global__ __launch_bounds__(256)
void softmax_rows(const float* __restrict__ scores, __nv_bfloat16* __restrict__ phi,
                  __nv_bfloat16* __restrict__ plo)
{
    __shared__ float red[8];
    const size_t row = blockIdx.x;
    const float4* p4 = (const float4*)(scores + row * (size_t)SS);
    const int tid = threadIdx.x;

    float4 a = p4[tid];          // cols 4*tid .. 4*tid+3
    float4 b = p4[tid + 256];    // cols 1024+4*tid .. +3
    float v[8] = {a.x, a.y, a.z, a.w, b.x, b.y, b.z, b.w};

    // block max
    float m = v[0];
#pragma unroll
    for (int i = 1; i < 8; ++i) m = fmaxf(m, v[i]);
#pragma unroll
    for (int o = 16; o; o >>= 1) m = fmaxf(m, __shfl_xor_sync(0xffffffffu, m, o));
    if ((tid & 31) == 0) red[tid >> 5] = m;
    __syncthreads();
    m = red[0];
#pragma unroll
    for (int i = 1; i < 8; ++i) m = fmaxf(m, red[i]);
    __syncthreads();

    // exp + block sum (values stay in registers)
    float s = 0.f;
#pragma unroll
    for (int i = 0; i < 8; ++i) {
        v[i] = __expf(v[i] - m);
        s += v[i];
    }
#pragma unroll
    for (int o = 16; o; o >>= 1) s += __shfl_xor_sync(0xffffffffu, s, o);
    if ((tid & 31) == 0) red[tid >> 5] = s;
    __syncthreads();
    s = 0.f;
#pragma unroll
    for (int i = 0; i < 8; ++i) s += red[i];
    const float inv = 1.f / s;

    // write hi/lo split, coalesced bf16x2 stores
    __nv_bfloat16* oh = phi + row * (size_t)SS;
    __nv_bfloat16* ol = plo + row * (size_t)SS;
#pragma unroll
    for (int half = 0; half < 2; ++half) {
        const int base = half * 1024 + tid * 4;
#pragma unroll
        for (int j = 0; j < 2; ++j) {
            const float x0 = v[half * 4 + j * 2 + 0] * inv;
            const float x1 = v[half * 4 + j * 2 + 1] * inv;
            const __nv_bfloat16 h0 = __float2bfloat16(x0);
            const __nv_bfloat16 h1 = __float2bfloat16(x1);
            const __nv_bfloat16 l0 = __float2bfloat16(x0 - __bfloat162float(h0));
            const __nv_bfloat16 l1 = __float2bfloat16(x1 - __bfloat162float(h1));
            *(__nv_bfloat162*)(oh + base + j * 2) = __halves2bfloat162(h0, h1);
            *(__nv_bfloat162*)(ol + base + j * 2) = __halves2bfloat162(l0, l1);
        }
    }
}

// ---------------------------------------------------------------------------
extern "C" void kernel_launch(void* const* d_in, const int* in_sizes, int n_in,
                              void* d_out, int out_size)
{
    const float* h = (const float*)d_in[0];   // [B,S,D]
    const float* W = (const float*)d_in[1];   // [D,D]
    float* out = (float*)d_out;               // [B,S,D]

    __nv_bfloat16 *h_hi, *h_lo, *ht_hi, *ht_lo, *Wt_hi, *Wt_lo, *hW_hi, *hW_lo, *P_hi, *P_lo;
    float* scores;
    cudaGetSymbolAddress((void**)&h_hi, g_h_hi);
    cudaGetSymbolAddress((void**)&h_lo, g_h_lo);
    cudaGetSymbolAddress((void**)&ht_hi, g_ht_hi);
    cudaGetSymbolAddress((void**)&ht_lo, g_ht_lo);
    cudaGetSymbolAddress((void**)&Wt_hi, g_Wt_hi);
    cudaGetSymbolAddress((void**)&Wt_lo, g_Wt_lo);
    cudaGetSymbolAddress((void**)&hW_hi, g_hW_hi);
    cudaGetSymbolAddress((void**)&hW_lo, g_hW_lo);
    cudaGetSymbolAddress((void**)&scores, g_scores);
    cudaGetSymbolAddress((void**)&P_hi, g_P_hi);
    cudaGetSymbolAddress((void**)&P_lo, g_P_lo);

    cudaFuncSetAttribute(gemm_mma<false, 128>, cudaFuncAttributeMaxDynamicSharedMemorySize,
                         GemmCfg<128>::SMEM);
    cudaFuncSetAttribute(gemm_mma<true, 64>,  cudaFuncAttributeMaxDynamicSharedMemorySize,
                         GemmCfg<64>::SMEM);
    cudaFuncSetAttribute(gemm_mma<false, 64>, cudaFuncAttributeMaxDynamicSharedMemorySize,
                         GemmCfg<64>::SMEM);

    // pre-passes: h transpose + fused row-major split; W transpose
    transpose_split<<<dim3(DD / 32, SS / 32, NB), dim3(32, 8)>>>(
        h, ht_hi, ht_lo, h_hi, h_lo, SS, DD, (long long)SS * DD, (long long)DD * SS);
    transpose_split<<<dim3(DD / 32, DD / 32, 1), dim3(32, 8)>>>(
        W, Wt_hi, Wt_lo, nullptr, nullptr, DD, DD, 0, 0);

    // 1) hW = h @ W : M=16384, N=800, K=800; BN=64 tiles (13 N-tiles)
    gemm_mma<true, 64><<<dim3(13, 128, 1), 128, GemmCfg<64>::SMEM>>>(
        h_hi, h_lo, Wt_hi, Wt_lo, nullptr, hW_hi, hW_lo,
        DD, DD, DD, DD, DD, 0, 0, 0);

    // 2) scores[b] = hW[b] @ h[b]^T : M=N=2048, K=800; BN=128 (best wave fit)
    gemm_mma<false, 128><<<dim3(16, 16, NB), 256, GemmCfg<128>::SMEM>>>(
        hW_hi, hW_lo, h_hi, h_lo, scores, nullptr, nullptr,
        SS, DD, DD, DD, SS,
        (long long)SS * DD, (long long)SS * DD, (long long)SS * SS);

    // 3) single-pass softmax + bf16 hi/lo split
    softmax_rows<<<NB * SS, 256>>>(scores, P_hi, P_lo);

    // 4) out[b] = P[b] @ h[b] : M=2048, N=800, K=2048; BN=64 tiles
    gemm_mma<false, 64><<<dim3(13, 16, NB), 128, GemmCfg<64>::SMEM>>>(
        P_hi, P_lo, ht_hi, ht_lo, out, nullptr, nullptr,
        DD, SS, SS, SS, DD,
        (long long)SS * SS, (long long)DD * SS, (long long)SS * DD);
}